// round 5
// baseline (speedup 1.0000x reference)
#include <cuda_runtime.h>

// ---------------------------------------------------------------------------
// GCNEncoder, CSR-based, FFMA2 (packed f32x2) GEMMs.
//   dinv[i] = rsqrt(indeg[i] + 1)
//   layer(X,W,b): H = X@W
//     out[i] = dinv[i]^2*H[i] + sum_{e: dst=i} dinv[src]*dinv[i]*H[src] + b
//   out = layer2( relu(layer1(x)) )
// edge_index int32. Scratch = __device__ globals. Launch-only host code.
// ---------------------------------------------------------------------------

#define MAXN 50048
#define MAXE 800000
#define FIN  128
#define HID  128
#define FOUT 64

__device__ float  g_h1 [MAXN * HID];    // GEMM1 out
__device__ float  g_agg[MAXN * HID];    // layer1 aggregated+relu
__device__ float  g_h2 [MAXN * FOUT];   // GEMM2 out
__device__ float  g_dinv[MAXN];
__device__ int    g_deg [MAXN];
__device__ int    g_fill[MAXN];
__device__ int    g_rs  [MAXN + 1];     // CSR row starts (by dst)
__device__ int    g_bsum[256];
__device__ int    g_boff[256];
__device__ int    g_csrc[MAXE];
__device__ float  g_cnrm[MAXE];
// W interleaved over k-pairs: wi[k2][c] = {W[2k2][c], W[2k2+1][c]}
// W1: 64*128 float2 = 8192; W2: 64*64 = 4096. Stored as float4 (16B aligned).
__device__ float4 g_wi[(8192 + 4096) / 2];

// packed fp32x2 fma: d = a*b + d (componentwise, exact fp32)
__device__ __forceinline__ void fma2(unsigned long long& d,
                                     unsigned long long a, unsigned long long b) {
    asm("fma.rn.f32x2 %0, %1, %2, %0;" : "+l"(d) : "l"(a), "l"(b));
}
__device__ __forceinline__ float2 unpack2(unsigned long long v) {
    float2 r;
    asm("mov.b64 {%0, %1}, %2;" : "=f"(r.x), "=f"(r.y) : "l"(v));
    return r;
}

// ---------------------------------------------------------------------------
__global__ void deg_init_k(int n) {
    int i = blockIdx.x * blockDim.x + threadIdx.x;
    if (i < n) { g_deg[i] = 0; g_fill[i] = 0; }
}

__global__ void deg_count_k(const int* __restrict__ dst, int E) {
    int i = blockIdx.x * blockDim.x + threadIdx.x;
    if (i < E) atomicAdd(&g_deg[dst[i]], 1);
}

__global__ void dinv_k(int n) {
    int i = blockIdx.x * blockDim.x + threadIdx.x;
    if (i < n) g_dinv[i] = rsqrtf((float)(g_deg[i] + 1));
}

// Interleave W1/W2 into g_wi (one-time).
__global__ void wint_k(const float* __restrict__ W1, const float* __restrict__ W2) {
    int i = blockIdx.x * blockDim.x + threadIdx.x;
    float2* wi = reinterpret_cast<float2*>(g_wi);
    if (i < 8192) {                       // W1: K2=64 rows x 128 cols
        int k2 = i >> 7, c = i & 127;
        wi[i] = make_float2(W1[(2 * k2) * 128 + c], W1[(2 * k2 + 1) * 128 + c]);
    } else if (i < 8192 + 4096) {         // W2: K2=64 rows x 64 cols
        int j = i - 8192;
        int k2 = j >> 6, c = j & 63;
        wi[i] = make_float2(W2[(2 * k2) * 64 + c], W2[(2 * k2 + 1) * 64 + c]);
    }
}

// --- exclusive scan of g_deg -> g_rs (3 kernels, 256/block) -----------------
__global__ void scan1_k(int n) {
    __shared__ int s[256];
    int b = blockIdx.x, t = threadIdx.x;
    int i = b * 256 + t;
    int v = (i < n) ? g_deg[i] : 0;
    s[t] = v;
    __syncthreads();
#pragma unroll
    for (int off = 1; off < 256; off <<= 1) {
        int add = (t >= off) ? s[t - off] : 0;
        __syncthreads();
        s[t] += add;
        __syncthreads();
    }
    if (i <= n) g_rs[i] = s[t] - v;
    if (t == 255) g_bsum[b] = s[255];
}

__global__ void scan2_k(int nb) {
    __shared__ int s[256];
    int t = threadIdx.x;
    int v = (t < nb) ? g_bsum[t] : 0;
    s[t] = v;
    __syncthreads();
#pragma unroll
    for (int off = 1; off < 256; off <<= 1) {
        int add = (t >= off) ? s[t - off] : 0;
        __syncthreads();
        s[t] += add;
        __syncthreads();
    }
    g_boff[t] = s[t] - v;
}

__global__ void scan3_k(int n, int E) {
    int i = blockIdx.x * blockDim.x + threadIdx.x;
    if (i < n) g_rs[i] += g_boff[i >> 8];
    if (i == 0) g_rs[n] = E;
}

__global__ void fill_k(const int* __restrict__ src, const int* __restrict__ dst, int E) {
    int e = blockIdx.x * blockDim.x + threadIdx.x;
    if (e >= E) return;
    int d = dst[e], s = src[e];
    int slot = g_rs[d] + atomicAdd(&g_fill[d], 1);
    g_csrc[slot] = s;
    g_cnrm[slot] = g_dinv[s] * g_dinv[d];
}

// ---------------------------------------------------------------------------
// FFMA2 GEMM: O[n,NC] = X[n,K] @ W[K,NC], W pre-interleaved over k-pairs.
// 256 thr; CG=NC/4 col-groups; TG=256/CG; RPB=64 rows/block; RPT=64/TG rows/thr.
// acc[r][c] is f32x2 holding {even-k partial, odd-k partial}; summed at end.
// x pairs: LDS.64 from row-major smem (free pairing). W: LDG.128 x2, L1-hot.
template <int K, int NC, bool XG, bool OG>
__global__ void __launch_bounds__(256)
gemm_k(const float* __restrict__ Xext, float* __restrict__ Oext,
       int wioff4, int n) {
    constexpr int CG  = NC / 4;
    constexpr int TG  = 256 / CG;
    constexpr int RPB = 64;
    constexpr int RPT = RPB / TG;   // 8 (NC=128) or 4 (NC=64)
    constexpr int K2  = K / 2;
    __shared__ float xs[RPB][K];

    const float* X = XG ? g_agg : Xext;
    float*       O = OG ? (NC == 128 ? g_h1 : g_h2) : Oext;

    const int row0 = blockIdx.x * RPB;
    {   // cooperative float4 tile load
        const int nf4 = RPB * (K / 4);
        const float4* X4 = reinterpret_cast<const float4*>(X);
        for (int idx = threadIdx.x; idx < nf4; idx += 256) {
            int rr = idx / (K / 4), kk = idx % (K / 4);
            int grow = row0 + rr;
            float4 v = make_float4(0.f, 0.f, 0.f, 0.f);
            if (grow < n) v = X4[(long long)grow * (K / 4) + kk];
            reinterpret_cast<float4*>(&xs[rr][0])[kk] = v;
        }
    }
    __syncthreads();

    const int cg   = threadIdx.x % CG;
    const int trow = threadIdx.x / CG;
    const ulonglong2* __restrict__ Wi =
        reinterpret_cast<const ulonglong2*>(g_wi) + wioff4;

    unsigned long long acc[RPT][4];
#pragma unroll
    for (int r = 0; r < RPT; r++)
#pragma unroll
        for (int c = 0; c < 4; c++) acc[r][c] = 0ull;

    const unsigned long long* xr[RPT];
#pragma unroll
    for (int r = 0; r < RPT; r++)
        xr[r] = reinterpret_cast<const unsigned long long*>(&xs[trow * RPT + r][0]);

#pragma unroll 2
    for (int k2 = 0; k2 < K2; k2++) {
        ulonglong2 wa = __ldg(&Wi[k2 * (NC / 2) + 2 * cg]);     // cols c, c+1
        ulonglong2 wb = __ldg(&Wi[k2 * (NC / 2) + 2 * cg + 1]); // cols c+2, c+3
#pragma unroll
        for (int r = 0; r < RPT; r++) {
            unsigned long long xp = xr[r][k2];  // {x[row][2k2], x[row][2k2+1]}
            fma2(acc[r][0], xp, wa.x);
            fma2(acc[r][1], xp, wa.y);
            fma2(acc[r][2], xp, wb.x);
            fma2(acc[r][3], xp, wb.y);
        }
    }

#pragma unroll
    for (int r = 0; r < RPT; r++) {
        int grow = row0 + trow * RPT + r;
        if (grow < n) {
            float2 c0 = unpack2(acc[r][0]), c1 = unpack2(acc[r][1]);
            float2 c2 = unpack2(acc[r][2]), c3 = unpack2(acc[r][3]);
            float4 o = make_float4(c0.x + c0.y, c1.x + c1.y,
                                   c2.x + c2.y, c3.x + c3.y);
            reinterpret_cast<float4*>(O)[(long long)grow * CG + cg] = o;
        }
    }
}

// ---------------------------------------------------------------------------
// CSR aggregation, fused self-loop + bias (+relu). GROUP=F/4 lanes per node.
template <int F, bool RELU, bool HG, bool OG>
__global__ void __launch_bounds__(256)
agg_k(float* __restrict__ Oext, const float* __restrict__ b, int n) {
    const float* H = HG ? g_h1 : g_h2;
    float*       O = OG ? g_agg : Oext;
    constexpr int GROUP = F / 4;
    int gtid = blockIdx.x * blockDim.x + threadIdx.x;
    int node = gtid / GROUP;
    int lane = gtid % GROUP;
    if (node >= n) return;

    const float4* __restrict__ H4 = reinterpret_cast<const float4*>(H);
    float d = g_dinv[node];
    float s2 = d * d;
    float4 h0 = H4[(long long)node * GROUP + lane];
    float4 acc = make_float4(h0.x * s2, h0.y * s2, h0.z * s2, h0.w * s2);

    int p  = g_rs[node];
    int p1 = g_rs[node + 1];
    for (; p + 3 < p1; p += 4) {                 // 4-way MLP vs L2 latency
        int   sA = g_csrc[p],   sB = g_csrc[p+1], sC = g_csrc[p+2], sD = g_csrc[p+3];
        float nA = g_cnrm[p],   nB = g_cnrm[p+1], nC = g_cnrm[p+2], nD = g_cnrm[p+3];
        float4 hA = H4[(long long)sA * GROUP + lane];
        float4 hB = H4[(long long)sB * GROUP + lane];
        float4 hC = H4[(long long)sC * GROUP + lane];
        float4 hD = H4[(long long)sD * GROUP + lane];
        acc.x += nA*hA.x + nB*hB.x + nC*hC.x + nD*hD.x;
        acc.y += nA*hA.y + nB*hB.y + nC*hC.y + nD*hD.y;
        acc.z += nA*hA.z + nB*hB.z + nC*hC.z + nD*hD.z;
        acc.w += nA*hA.w + nB*hB.w + nC*hC.w + nD*hD.w;
    }
    for (; p < p1; p++) {
        int   s = g_csrc[p];
        float nm = g_cnrm[p];
        float4 h = H4[(long long)s * GROUP + lane];
        acc.x += nm*h.x; acc.y += nm*h.y; acc.z += nm*h.z; acc.w += nm*h.w;
    }

    float4 bb = reinterpret_cast<const float4*>(b)[lane];
    acc.x += bb.x; acc.y += bb.y; acc.z += bb.z; acc.w += bb.w;
    if (RELU) {
        acc.x = fmaxf(acc.x, 0.f); acc.y = fmaxf(acc.y, 0.f);
        acc.z = fmaxf(acc.z, 0.f); acc.w = fmaxf(acc.w, 0.f);
    }
    reinterpret_cast<float4*>(O)[(long long)node * GROUP + lane] = acc;
}

// ---------------------------------------------------------------------------
extern "C" void kernel_launch(void* const* d_in, const int* in_sizes, int n_in,
                              void* d_out, int out_size) {
    const float* x   = (const float*)d_in[0];
    const int*   ei  = (const int*)d_in[1];   // int32 [2, E]
    const float* W1  = (const float*)d_in[2];
    const float* b1  = (const float*)d_in[3];
    const float* W2  = (const float*)d_in[4];
    const float* b2  = (const float*)d_in[5];
    float*       out = (float*)d_out;

    const int n = in_sizes[0] / FIN;
    const int E = in_sizes[1] / 2;
    const int* src = ei;
    const int* dst = ei + E;

    const int T = 256;
    auto cdiv = [](long long a, long long b) { return (int)((a + b - 1) / b); };
    const int nb = cdiv(n, 256);

    // prep: degrees, norm, W interleave, CSR
    deg_init_k <<<cdiv(n, T), T>>>(n);
    deg_count_k<<<cdiv(E, T), T>>>(dst, E);
    wint_k     <<<cdiv(8192 + 4096, T), T>>>(W1, W2);
    dinv_k     <<<cdiv(n, T), T>>>(n);
    scan1_k    <<<nb, 256>>>(n);
    scan2_k    <<<1, 256>>>(nb);
    scan3_k    <<<cdiv(n, T), T>>>(n, E);
    fill_k     <<<cdiv(E, T), T>>>(src, dst, E);

    // layer 1: x @ W1 -> g_h1; aggregate(+b1, relu) -> g_agg
    gemm_k<FIN, HID, false, true><<<cdiv(n, 64), 256>>>(x, nullptr, 0, n);
    agg_k<HID, true, true, true><<<cdiv((long long)n * (HID / 4), T), T>>>(nullptr, b1, n);

    // layer 2: g_agg @ W2 -> g_h2; aggregate(+b2) -> out
    gemm_k<HID, FOUT, true, true><<<cdiv(n, 64), 256>>>(nullptr, nullptr, 8192 / 2, n);
    agg_k<FOUT, false, false, false><<<cdiv((long long)n * (FOUT / 4), T), T>>>(out, b2, n);
}

// round 6
// speedup vs baseline: 1.0801x; 1.0801x over previous
#include <cuda_runtime.h>

// ---------------------------------------------------------------------------
// GCNEncoder, CSR-based (packed edge records), fp32 register-tiled GEMMs.
//   dinv[i] = rsqrt(indeg[i] + 1)
//   layer(X,W,b): H = X@W
//     out[i] = dinv[i]^2*H[i] + sum_{e: dst=i} dinv[src]*dinv[i]*H[src] + b
//   out = layer2( relu(layer1(x)) )
// edge_index int32. Scratch = __device__ globals. Launch-only host code.
// ---------------------------------------------------------------------------

#define MAXN 50048
#define MAXE 800000
#define FIN  128
#define HID  128
#define FOUT 64

__device__ float g_h1 [MAXN * HID];    // GEMM1 out
__device__ float g_agg[MAXN * HID];    // layer1 aggregated+relu
__device__ float g_h2 [MAXN * FOUT];   // GEMM2 out
__device__ float g_dinv[MAXN];
__device__ int   g_deg [MAXN];
__device__ int   g_fill[MAXN];
__device__ int   g_rs  [MAXN + 1];     // CSR row starts (by dst)
__device__ int   g_bsum[256];
__device__ int   g_boff[256];
__device__ int2  g_cpak[MAXE];         // {src, float_bits(norm)} per CSR slot

// ---------------------------------------------------------------------------
__global__ void deg_init_k(int n) {
    int i = blockIdx.x * blockDim.x + threadIdx.x;
    if (i < n) { g_deg[i] = 0; g_fill[i] = 0; }
}

__global__ void deg_count_k(const int* __restrict__ dst, int E) {
    int i = blockIdx.x * blockDim.x + threadIdx.x;
    if (i < E) atomicAdd(&g_deg[dst[i]], 1);
}

// --- exclusive scan of g_deg -> g_rs, fused dinv ---------------------------
__global__ void scan1_k(int n) {
    __shared__ int s[256];
    int b = blockIdx.x, t = threadIdx.x;
    int i = b * 256 + t;
    int v = (i < n) ? g_deg[i] : 0;
    if (i < n) g_dinv[i] = rsqrtf((float)(v + 1));   // fused dinv
    s[t] = v;
    __syncthreads();
#pragma unroll
    for (int off = 1; off < 256; off <<= 1) {
        int add = (t >= off) ? s[t - off] : 0;
        __syncthreads();
        s[t] += add;
        __syncthreads();
    }
    if (i <= n) g_rs[i] = s[t] - v;
    if (t == 255) g_bsum[b] = s[255];
}

__global__ void scan2_k(int nb) {
    __shared__ int s[256];
    int t = threadIdx.x;
    int v = (t < nb) ? g_bsum[t] : 0;
    s[t] = v;
    __syncthreads();
#pragma unroll
    for (int off = 1; off < 256; off <<= 1) {
        int add = (t >= off) ? s[t - off] : 0;
        __syncthreads();
        s[t] += add;
        __syncthreads();
    }
    g_boff[t] = s[t] - v;
}

__global__ void scan3_k(int n, int E) {
    int i = blockIdx.x * blockDim.x + threadIdx.x;
    if (i < n) g_rs[i] += g_boff[i >> 8];
    if (i == 0) g_rs[n] = E;
}

__global__ void fill_k(const int* __restrict__ src, const int* __restrict__ dst, int E) {
    int e = blockIdx.x * blockDim.x + threadIdx.x;
    if (e >= E) return;
    int d = dst[e], s = src[e];
    int slot = g_rs[d] + atomicAdd(&g_fill[d], 1);
    float nm = g_dinv[s] * g_dinv[d];
    g_cpak[slot] = make_int2(s, __float_as_int(nm));
}

// ---------------------------------------------------------------------------
// Register-tiled GEMM: O[n,NC] = X[n,K] @ W[K,NC].  256 threads/block.
// CG=NC/4 col-groups; TG=256/CG thread-rows; RPT=64/TG rows/thread (stride TG).
// W float4 loaded once per k-step, reused RPT times from registers.
template <int K, int NC, bool XG, bool OG>
__global__ void __launch_bounds__(256)
gemm_k(const float* __restrict__ Xext, float* __restrict__ Oext,
       const float* __restrict__ W, int n) {
    const float* X = XG ? g_agg : Xext;
    float*       O = OG ? (NC == 128 ? g_h1 : g_h2) : Oext;

    constexpr int CG  = NC / 4;
    constexpr int TG  = 256 / CG;
    constexpr int RPB = 64;
    constexpr int RPT = RPB / TG;
    __shared__ float xs[RPB][K];

    const int row0 = blockIdx.x * RPB;
    {
        const int nf4 = RPB * (K / 4);
        const float4* X4 = reinterpret_cast<const float4*>(X);
        for (int idx = threadIdx.x; idx < nf4; idx += 256) {
            int rr = idx / (K / 4), kk = idx % (K / 4);
            int grow = row0 + rr;
            float4 v = make_float4(0.f, 0.f, 0.f, 0.f);
            if (grow < n) v = X4[(long long)grow * (K / 4) + kk];
            reinterpret_cast<float4*>(&xs[rr][0])[kk] = v;
        }
    }
    __syncthreads();

    const int cg   = threadIdx.x % CG;
    const int trow = threadIdx.x / CG;
    const float4* __restrict__ W4 = reinterpret_cast<const float4*>(W);

    float4 acc[RPT];
#pragma unroll
    for (int r = 0; r < RPT; r++) acc[r] = make_float4(0.f, 0.f, 0.f, 0.f);

#pragma unroll 4
    for (int k4 = 0; k4 < K / 4; k4++) {
        float4 w0 = W4[(k4 * 4 + 0) * CG + cg];
        float4 w1 = W4[(k4 * 4 + 1) * CG + cg];
        float4 w2 = W4[(k4 * 4 + 2) * CG + cg];
        float4 w3 = W4[(k4 * 4 + 3) * CG + cg];
#pragma unroll
        for (int r = 0; r < RPT; r++) {
            float4 xv = reinterpret_cast<const float4*>(&xs[trow + r * TG][0])[k4];
            acc[r].x += xv.x * w0.x + xv.y * w1.x + xv.z * w2.x + xv.w * w3.x;
            acc[r].y += xv.x * w0.y + xv.y * w1.y + xv.z * w2.y + xv.w * w3.y;
            acc[r].z += xv.x * w0.z + xv.y * w1.z + xv.z * w2.z + xv.w * w3.z;
            acc[r].w += xv.x * w0.w + xv.y * w1.w + xv.z * w2.w + xv.w * w3.w;
        }
    }

#pragma unroll
    for (int r = 0; r < RPT; r++) {
        int grow = row0 + trow + r * TG;
        if (grow < n)
            reinterpret_cast<float4*>(O)[(long long)grow * CG + cg] = acc[r];
    }
}

// ---------------------------------------------------------------------------
// CSR aggregation, fused self-loop + bias (+relu). GROUP=F/4 lanes per node.
// Packed edge records (src, norm) in one 8B load; 8-way unrolled gather.
template <int F, bool RELU, bool HG, bool OG>
__global__ void __launch_bounds__(256)
agg_k(float* __restrict__ Oext, const float* __restrict__ b, int n) {
    const float* H = HG ? g_h1 : g_h2;
    float*       O = OG ? g_agg : Oext;
    constexpr int GROUP = F / 4;
    int gtid = blockIdx.x * blockDim.x + threadIdx.x;
    int node = gtid / GROUP;
    int lane = gtid % GROUP;
    if (node >= n) return;

    const float4* __restrict__ H4 = reinterpret_cast<const float4*>(H);
    const int2*   __restrict__ CP = g_cpak;
    float d = g_dinv[node];
    float s2 = d * d;
    float4 h0 = H4[(long long)node * GROUP + lane];
    float4 acc = make_float4(h0.x * s2, h0.y * s2, h0.z * s2, h0.w * s2);

    int p  = g_rs[node];
    int p1 = g_rs[node + 1];

    for (; p + 7 < p1; p += 8) {
        int2 e0 = CP[p],   e1 = CP[p+1], e2 = CP[p+2], e3 = CP[p+3];
        int2 e4 = CP[p+4], e5 = CP[p+5], e6 = CP[p+6], e7 = CP[p+7];
        float4 hA = H4[(long long)e0.x * GROUP + lane];
        float4 hB = H4[(long long)e1.x * GROUP + lane];
        float4 hC = H4[(long long)e2.x * GROUP + lane];
        float4 hD = H4[(long long)e3.x * GROUP + lane];
        float4 hE = H4[(long long)e4.x * GROUP + lane];
        float4 hF = H4[(long long)e5.x * GROUP + lane];
        float4 hG = H4[(long long)e6.x * GROUP + lane];
        float4 hH = H4[(long long)e7.x * GROUP + lane];
        float nA = __int_as_float(e0.y), nB = __int_as_float(e1.y);
        float nC = __int_as_float(e2.y), nD = __int_as_float(e3.y);
        float nE = __int_as_float(e4.y), nF = __int_as_float(e5.y);
        float nG = __int_as_float(e6.y), nH = __int_as_float(e7.y);
        acc.x += nA*hA.x + nB*hB.x + nC*hC.x + nD*hD.x
               + nE*hE.x + nF*hF.x + nG*hG.x + nH*hH.x;
        acc.y += nA*hA.y + nB*hB.y + nC*hC.y + nD*hD.y
               + nE*hE.y + nF*hF.y + nG*hG.y + nH*hH.y;
        acc.z += nA*hA.z + nB*hB.z + nC*hC.z + nD*hD.z
               + nE*hE.z + nF*hF.z + nG*hG.z + nH*hH.z;
        acc.w += nA*hA.w + nB*hB.w + nC*hC.w + nD*hD.w
               + nE*hE.w + nF*hF.w + nG*hG.w + nH*hH.w;
    }
    for (; p + 3 < p1; p += 4) {
        int2 e0 = CP[p], e1 = CP[p+1], e2 = CP[p+2], e3 = CP[p+3];
        float4 hA = H4[(long long)e0.x * GROUP + lane];
        float4 hB = H4[(long long)e1.x * GROUP + lane];
        float4 hC = H4[(long long)e2.x * GROUP + lane];
        float4 hD = H4[(long long)e3.x * GROUP + lane];
        float nA = __int_as_float(e0.y), nB = __int_as_float(e1.y);
        float nC = __int_as_float(e2.y), nD = __int_as_float(e3.y);
        acc.x += nA*hA.x + nB*hB.x + nC*hC.x + nD*hD.x;
        acc.y += nA*hA.y + nB*hB.y + nC*hC.y + nD*hD.y;
        acc.z += nA*hA.z + nB*hB.z + nC*hC.z + nD*hD.z;
        acc.w += nA*hA.w + nB*hB.w + nC*hC.w + nD*hD.w;
    }
    for (; p < p1; p++) {
        int2 e = CP[p];
        float nm = __int_as_float(e.y);
        float4 h = H4[(long long)e.x * GROUP + lane];
        acc.x += nm*h.x; acc.y += nm*h.y; acc.z += nm*h.z; acc.w += nm*h.w;
    }

    float4 bb = reinterpret_cast<const float4*>(b)[lane];
    acc.x += bb.x; acc.y += bb.y; acc.z += bb.z; acc.w += bb.w;
    if (RELU) {
        acc.x = fmaxf(acc.x, 0.f); acc.y = fmaxf(acc.y, 0.f);
        acc.z = fmaxf(acc.z, 0.f); acc.w = fmaxf(acc.w, 0.f);
    }
    reinterpret_cast<float4*>(O)[(long long)node * GROUP + lane] = acc;
}

// ---------------------------------------------------------------------------
extern "C" void kernel_launch(void* const* d_in, const int* in_sizes, int n_in,
                              void* d_out, int out_size) {
    const float* x   = (const float*)d_in[0];
    const int*   ei  = (const int*)d_in[1];   // int32 [2, E]
    const float* W1  = (const float*)d_in[2];
    const float* b1  = (const float*)d_in[3];
    const float* W2  = (const float*)d_in[4];
    const float* b2  = (const float*)d_in[5];
    float*       out = (float*)d_out;

    const int n = in_sizes[0] / FIN;
    const int E = in_sizes[1] / 2;
    const int* src = ei;
    const int* dst = ei + E;

    const int T = 256;
    auto cdiv = [](long long a, long long b) { return (int)((a + b - 1) / b); };
    const int nb = cdiv(n, 256);

    // Launch order chosen so gemm_k<128,128> is the 4th launch (profiled slot).
    deg_init_k <<<cdiv(n, T), T>>>(n);                                   // 1
    deg_count_k<<<cdiv(E, T), T>>>(dst, E);                              // 2
    scan1_k    <<<nb, 256>>>(n);                                         // 3 (+dinv)
    gemm_k<FIN, HID, false, true><<<cdiv(n, 64), 256>>>(x, nullptr, W1, n); // 4 <- profiled
    scan2_k    <<<1, 256>>>(nb);                                         // 5
    scan3_k    <<<cdiv(n, T), T>>>(n, E);                                // 6
    fill_k     <<<cdiv(E, T), T>>>(src, dst, E);                         // 7
    agg_k<HID, true, true, true><<<cdiv((long long)n * (HID / 4), T), T>>>(nullptr, b1, n); // 8
    gemm_k<HID, FOUT, true, true><<<cdiv(n, 64), 256>>>(nullptr, nullptr, W2, n);           // 9
    agg_k<FOUT, false, false, false><<<cdiv((long long)n * (FOUT / 4), T), T>>>(out, b2, n);// 10
}

// round 7
// speedup vs baseline: 1.2318x; 1.1404x over previous
#include <cuda_runtime.h>

// ---------------------------------------------------------------------------
// GCNEncoder, CSR aggregation + split-TF32 (3xTF32) tensor-core GEMMs.
//   dinv[i] = rsqrt(indeg[i] + 1)
//   layer(X,W,b): H = X@W
//     out[i] = dinv[i]^2*H[i] + sum_{e: dst=i} dinv[src]*dinv[i]*H[src] + b
//   out = layer2( relu(layer1(x)) )
// edge_index int32. Scratch = __device__ globals. Launch-only host code.
// ---------------------------------------------------------------------------

#define MAXN 50048
#define MAXE 800000
#define FIN  128
#define HID  128
#define FOUT 64

__device__ float g_h1 [MAXN * HID];
__device__ float g_agg[MAXN * HID];
__device__ float g_h2 [MAXN * FOUT];
__device__ float g_dinv[MAXN];
__device__ int   g_deg [MAXN];
__device__ int   g_fill[MAXN];
__device__ int   g_rs  [MAXN + 1];
__device__ int   g_bsum[256];
__device__ int   g_boff[256];
__device__ int2  g_cpak[MAXE];         // {src, float_bits(norm)}

// ---------------------------------------------------------------------------
__device__ __forceinline__ unsigned f2tf32(float f) {
    unsigned r;
    asm("cvt.rna.tf32.f32 %0, %1;" : "=r"(r) : "f"(f));
    return r;
}

__device__ __forceinline__ void mma_tf32(float (&d)[4], const unsigned (&a)[4],
                                         unsigned b0, unsigned b1) {
    asm volatile(
        "mma.sync.aligned.m16n8k8.row.col.f32.tf32.tf32.f32 "
        "{%0,%1,%2,%3}, {%4,%5,%6,%7}, {%8,%9}, {%0,%1,%2,%3};\n"
        : "+f"(d[0]), "+f"(d[1]), "+f"(d[2]), "+f"(d[3])
        : "r"(a[0]), "r"(a[1]), "r"(a[2]), "r"(a[3]), "r"(b0), "r"(b1));
}

// ---------------------------------------------------------------------------
__global__ void deg_init_k(int n) {
    int i = blockIdx.x * blockDim.x + threadIdx.x;
    if (i < n) { g_deg[i] = 0; g_fill[i] = 0; }
}

__global__ void deg_count_k(const int* __restrict__ dst, int E) {
    int i = blockIdx.x * blockDim.x + threadIdx.x;
    if (i < E) atomicAdd(&g_deg[dst[i]], 1);
}

// exclusive scan of g_deg -> g_rs, fused dinv
__global__ void scan1_k(int n) {
    __shared__ int s[256];
    int b = blockIdx.x, t = threadIdx.x;
    int i = b * 256 + t;
    int v = (i < n) ? g_deg[i] : 0;
    if (i < n) g_dinv[i] = rsqrtf((float)(v + 1));
    s[t] = v;
    __syncthreads();
#pragma unroll
    for (int off = 1; off < 256; off <<= 1) {
        int add = (t >= off) ? s[t - off] : 0;
        __syncthreads();
        s[t] += add;
        __syncthreads();
    }
    if (i <= n) g_rs[i] = s[t] - v;
    if (t == 255) g_bsum[b] = s[255];
}

__global__ void scan2_k(int nb) {
    __shared__ int s[256];
    int t = threadIdx.x;
    int v = (t < nb) ? g_bsum[t] : 0;
    s[t] = v;
    __syncthreads();
#pragma unroll
    for (int off = 1; off < 256; off <<= 1) {
        int add = (t >= off) ? s[t - off] : 0;
        __syncthreads();
        s[t] += add;
        __syncthreads();
    }
    g_boff[t] = s[t] - v;
}

__global__ void scan3_k(int n, int E) {
    int i = blockIdx.x * blockDim.x + threadIdx.x;
    if (i < n) g_rs[i] += g_boff[i >> 8];
    if (i == 0) g_rs[n] = E;
}

__global__ void fill_k(const int* __restrict__ src, const int* __restrict__ dst, int E) {
    int e = blockIdx.x * blockDim.x + threadIdx.x;
    if (e >= E) return;
    int d = dst[e], s = src[e];
    int slot = g_rs[d] + atomicAdd(&g_fill[d], 1);
    float nm = g_dinv[s] * g_dinv[d];
    g_cpak[slot] = make_int2(s, __float_as_int(nm));
}

// ---------------------------------------------------------------------------
// Split-TF32 tensor GEMM: O[n,NC] = X[n,K=128] @ W[128,NC].
// 128 threads = 4 warps; M-tile 64 (16 rows/warp), full NC per warp (NT n-tiles).
// K processed in chunks of 16 (2 mma k-steps). W converted to tf32 hi/lo once
// per chunk into smem, stored as {k, k+4} float2 pairs (single LDS.64 b-frags).
// D += Ahi*Bhi + Alo*Bhi + Ahi*Blo  (3xTF32, ~fp32 accuracy).
template <int NC, bool XG, bool OG>
__global__ void __launch_bounds__(128)
gemm_tc_k(const float* __restrict__ Xext, float* __restrict__ Oext,
          const float* __restrict__ W, int n) {
    constexpr int K  = 128;
    constexpr int KC = 16;
    constexpr int NT = NC / 8;
    constexpr int AS = 20;        // A stride (floats): banks (20g+r)%32 distinct
    constexpr int BS = NC + 4;    // B stride (float2): phase-conflict-free
    __shared__ float  As[64][AS];
    __shared__ float2 Bhi[2][4][BS];
    __shared__ float2 Blo[2][4][BS];

    const float* X = XG ? g_agg : Xext;
    float*       O = OG ? (NC == 128 ? g_h1 : g_h2) : Oext;

    const int tid  = threadIdx.x;
    const int wid  = tid >> 5;
    const int lane = tid & 31;
    const int gq   = lane >> 2;   // 0..7
    const int r    = lane & 3;    // 0..3
    const int row0 = blockIdx.x * 64;

    float acc[NT][4];
#pragma unroll
    for (int nt = 0; nt < NT; nt++)
#pragma unroll
        for (int c = 0; c < 4; c++) acc[nt][c] = 0.f;

    for (int k0 = 0; k0 < K; k0 += KC) {
        __syncthreads();
        // A chunk: 64 rows x 16 k (4 float4/row)
        for (int idx = tid; idx < 64 * 4; idx += 128) {
            int rr = idx >> 2, j = idx & 3;
            int grow = row0 + rr;
            float4 v = make_float4(0.f, 0.f, 0.f, 0.f);
            if (grow < n)
                v = reinterpret_cast<const float4*>(X)[grow * (K / 4) + k0 / 4 + j];
            *reinterpret_cast<float4*>(&As[rr][j * 4]) = v;
        }
        // B chunk: rows k0..k0+15, paired {k, k+4}, converted to tf32 hi/lo
        for (int idx = tid; idx < 8 * NC; idx += 128) {
            int nn = idx % NC;
            int sr = idx / NC;            // 0..7
            int s  = sr >> 2, rr = sr & 3;
            float w0 = W[(k0 + 8 * s + rr) * NC + nn];
            float w1 = W[(k0 + 8 * s + rr + 4) * NC + nn];
            unsigned h0 = f2tf32(w0), h1 = f2tf32(w1);
            Bhi[s][rr][nn] = make_float2(__uint_as_float(h0), __uint_as_float(h1));
            Blo[s][rr][nn] = make_float2(
                __uint_as_float(f2tf32(w0 - __uint_as_float(h0))),
                __uint_as_float(f2tf32(w1 - __uint_as_float(h1))));
        }
        __syncthreads();

#pragma unroll
        for (int s = 0; s < 2; s++) {
            float a0 = As[wid * 16 + gq][8 * s + r];
            float a1 = As[wid * 16 + gq + 8][8 * s + r];
            float a2 = As[wid * 16 + gq][8 * s + r + 4];
            float a3 = As[wid * 16 + gq + 8][8 * s + r + 4];
            unsigned ah[4] = {f2tf32(a0), f2tf32(a1), f2tf32(a2), f2tf32(a3)};
            unsigned al[4] = {
                f2tf32(a0 - __uint_as_float(ah[0])),
                f2tf32(a1 - __uint_as_float(ah[1])),
                f2tf32(a2 - __uint_as_float(ah[2])),
                f2tf32(a3 - __uint_as_float(ah[3]))};
#pragma unroll
            for (int nt = 0; nt < NT; nt++) {
                float2 bh = Bhi[s][r][nt * 8 + gq];
                float2 bl = Blo[s][r][nt * 8 + gq];
                unsigned bh0 = __float_as_uint(bh.x), bh1 = __float_as_uint(bh.y);
                unsigned bl0 = __float_as_uint(bl.x), bl1 = __float_as_uint(bl.y);
                mma_tf32(acc[nt], ah, bh0, bh1);
                mma_tf32(acc[nt], al, bh0, bh1);
                mma_tf32(acc[nt], ah, bl0, bl1);
            }
        }
    }

    // epilogue: c0,c1 -> (row, 2r), c2,c3 -> (row+8, 2r)
    const int rA = row0 + wid * 16 + gq;
    const int rB = rA + 8;
#pragma unroll
    for (int nt = 0; nt < NT; nt++) {
        int col = nt * 8 + 2 * r;
        if (rA < n)
            *reinterpret_cast<float2*>(&O[rA * NC + col]) = make_float2(acc[nt][0], acc[nt][1]);
        if (rB < n)
            *reinterpret_cast<float2*>(&O[rB * NC + col]) = make_float2(acc[nt][2], acc[nt][3]);
    }
}

// ---------------------------------------------------------------------------
// CSR aggregation, fused self-loop + bias (+relu). GROUP=F/4 lanes per node.
template <int F, bool RELU, bool HG, bool OG>
__global__ void __launch_bounds__(256)
agg_k(float* __restrict__ Oext, const float* __restrict__ b, int n) {
    const float* H = HG ? g_h1 : g_h2;
    float*       O = OG ? g_agg : Oext;
    constexpr int GROUP = F / 4;
    int gtid = blockIdx.x * blockDim.x + threadIdx.x;
    int node = gtid / GROUP;
    int lane = gtid % GROUP;
    if (node >= n) return;

    const float4* __restrict__ H4 = reinterpret_cast<const float4*>(H);
    const int2*   __restrict__ CP = g_cpak;
    float d = g_dinv[node];
    float s2 = d * d;
    float4 h0 = H4[(long long)node * GROUP + lane];
    float4 acc = make_float4(h0.x * s2, h0.y * s2, h0.z * s2, h0.w * s2);

    int p  = g_rs[node];
    int p1 = g_rs[node + 1];
    for (; p + 3 < p1; p += 4) {
        int2 e0 = CP[p], e1 = CP[p+1], e2 = CP[p+2], e3 = CP[p+3];
        float4 hA = H4[(long long)e0.x * GROUP + lane];
        float4 hB = H4[(long long)e1.x * GROUP + lane];
        float4 hC = H4[(long long)e2.x * GROUP + lane];
        float4 hD = H4[(long long)e3.x * GROUP + lane];
        float nA = __int_as_float(e0.y), nB = __int_as_float(e1.y);
        float nC = __int_as_float(e2.y), nD = __int_as_float(e3.y);
        acc.x += nA*hA.x + nB*hB.x + nC*hC.x + nD*hD.x;
        acc.y += nA*hA.y + nB*hB.y + nC*hC.y + nD*hD.y;
        acc.z += nA*hA.z + nB*hB.z + nC*hC.z + nD*hD.z;
        acc.w += nA*hA.w + nB*hB.w + nC*hC.w + nD*hD.w;
    }
    for (; p < p1; p++) {
        int2 e = CP[p];
        float nm = __int_as_float(e.y);
        float4 h = H4[(long long)e.x * GROUP + lane];
        acc.x += nm*h.x; acc.y += nm*h.y; acc.z += nm*h.z; acc.w += nm*h.w;
    }

    float4 bb = reinterpret_cast<const float4*>(b)[lane];
    acc.x += bb.x; acc.y += bb.y; acc.z += bb.z; acc.w += bb.w;
    if (RELU) {
        acc.x = fmaxf(acc.x, 0.f); acc.y = fmaxf(acc.y, 0.f);
        acc.z = fmaxf(acc.z, 0.f); acc.w = fmaxf(acc.w, 0.f);
    }
    reinterpret_cast<float4*>(O)[(long long)node * GROUP + lane] = acc;
}

// ---------------------------------------------------------------------------
extern "C" void kernel_launch(void* const* d_in, const int* in_sizes, int n_in,
                              void* d_out, int out_size) {
    const float* x   = (const float*)d_in[0];
    const int*   ei  = (const int*)d_in[1];   // int32 [2, E]
    const float* W1  = (const float*)d_in[2];
    const float* b1  = (const float*)d_in[3];
    const float* W2  = (const float*)d_in[4];
    const float* b2  = (const float*)d_in[5];
    float*       out = (float*)d_out;

    const int n = in_sizes[0] / FIN;
    const int E = in_sizes[1] / 2;
    const int* src = ei;
    const int* dst = ei + E;

    const int T = 256;
    auto cdiv = [](long long a, long long b) { return (int)((a + b - 1) / b); };
    const int nb = cdiv(n, 256);

    // gemm_tc_k<128> kept as 4th launch (ncu profiled slot).
    deg_init_k <<<cdiv(n, T), T>>>(n);                                    // 1
    deg_count_k<<<cdiv(E, T), T>>>(dst, E);                               // 2
    scan1_k    <<<nb, 256>>>(n);                                          // 3
    gemm_tc_k<HID, false, true><<<cdiv(n, 64), 128>>>(x, nullptr, W1, n); // 4 <- profiled
    scan2_k    <<<1, 256>>>(nb);                                          // 5
    scan3_k    <<<cdiv(n, T), T>>>(n, E);                                 // 6
    fill_k     <<<cdiv(E, T), T>>>(src, dst, E);                          // 7
    agg_k<HID, true, true, true><<<cdiv((long long)n * (HID / 4), T), T>>>(nullptr, b1, n); // 8
    gemm_tc_k<FOUT, true, true><<<cdiv(n, 64), 128>>>(nullptr, nullptr, W2, n);             // 9
    agg_k<FOUT, false, false, false><<<cdiv((long long)n * (FOUT / 4), T), T>>>(out, b2, n);// 10
}